// round 13
// baseline (speedup 1.0000x reference)
#include <cuda_runtime.h>
#include <cuda_bf16.h>

#define SEQ 2048
#define NB  4
#define NR  (SEQ*NB)   // 8192 rows, r = t*NB + b

// ------------------------- scratch (device globals) -------------------------
__device__ float g_preL [NR*512];
__device__ float g_lstmA[NR*128];
__device__ float g_lstmB[NR*128];
__device__ float g_xm   [NR*128];
__device__ float g_xz   [NR*512];
__device__ float g_xc   [NR*256];
__device__ float g_dbc  [NR*136];
__device__ float g_ymid [NR*256];
__device__ float g_mamba[NR*128];

// ------------------------- helpers -------------------------
__device__ __forceinline__ unsigned long long ffma2(unsigned long long a, unsigned long long b, unsigned long long c){
    unsigned long long d; asm("fma.rn.f32x2 %0, %1, %2, %3;" : "=l"(d) : "l"(a), "l"(b), "l"(c)); return d;
}
__device__ __forceinline__ unsigned long long fadd2(unsigned long long a, unsigned long long b){
    unsigned long long d; asm("add.rn.f32x2 %0, %1, %2;" : "=l"(d) : "l"(a), "l"(b)); return d;
}
__device__ __forceinline__ unsigned long long pk2(float lo, float hi){
    unsigned long long d; asm("mov.b64 %0, {%1, %2};" : "=l"(d) : "f"(lo), "f"(hi)); return d;
}
__device__ __forceinline__ float2 upk2(unsigned long long v){
    float2 r; asm("mov.b64 {%0, %1}, %2;" : "=f"(r.x), "=f"(r.y) : "l"(v)); return r;
}
__device__ __forceinline__ float ex2f(float x){
    float y; asm("ex2.approx.f32 %0, %1;" : "=f"(y) : "f"(x)); return y;
}
__device__ __forceinline__ float rcpf(float x){
    float y; asm("rcp.approx.f32 %0, %1;" : "=f"(y) : "f"(x)); return y;
}
__device__ __forceinline__ float tanha(float x){
    float y; asm("tanh.approx.f32 %0, %1;" : "=f"(y) : "f"(x)); return y;
}
__device__ __forceinline__ float sigm(float x){
    return rcpf(1.f + ex2f(-1.4426950408889634f * x));
}

// ------------------------- GEMM: C = A @ W^T (+bias1+bias2)(+act) ------------------
// tile 128(M) x 64(N), 256 threads, microtile 8x4, double-buffered k-tiles.
// A: [M, lda] row-major (first K cols), W: [N, K], C: [M, ldc]. M % 128 == 0.
// act: 0 = none, 1 = softplus
__global__ __launch_bounds__(256) void gemm_tn(
    const float* __restrict__ A, int lda,
    const float* __restrict__ W,
    const float* __restrict__ bias1,
    const float* __restrict__ bias2,
    float* __restrict__ C, int ldc,
    int M, int N, int K, int act)
{
    __shared__ float As[16][136];
    __shared__ float Ws[16][72];
    const int tid = threadIdx.x;
    const int tx = tid & 15, ty = tid >> 4;
    const int m0 = blockIdx.x * 128, n0 = blockIdx.y * 64;

    float acc[8][4];
#pragma unroll
    for (int i = 0; i < 8; i++)
#pragma unroll
        for (int j = 0; j < 4; j++) acc[i][j] = 0.f;

    float pa[8], pw[4];
#pragma unroll
    for (int i = 0; i < 8; i++) {
        int e = tid + i * 256, mm = e >> 4, kk = e & 15;
        pa[i] = (kk < K) ? A[(size_t)(m0 + mm) * lda + kk] : 0.f;
    }
#pragma unroll
    for (int i = 0; i < 4; i++) {
        int e = tid + i * 256, nn = e >> 4, kk = e & 15;
        pw[i] = (kk < K && n0 + nn < N) ? W[(size_t)(n0 + nn) * K + kk] : 0.f;
    }

    for (int k0 = 0; k0 < K; k0 += 16) {
#pragma unroll
        for (int i = 0; i < 8; i++) {
            int e = tid + i * 256;
            As[e & 15][e >> 4] = pa[i];
        }
#pragma unroll
        for (int i = 0; i < 4; i++) {
            int e = tid + i * 256;
            Ws[e & 15][e >> 4] = pw[i];
        }
        __syncthreads();

        int k1 = k0 + 16;
        if (k1 < K) {
#pragma unroll
            for (int i = 0; i < 8; i++) {
                int e = tid + i * 256, mm = e >> 4, kk = e & 15;
                pa[i] = (k1 + kk < K) ? A[(size_t)(m0 + mm) * lda + k1 + kk] : 0.f;
            }
#pragma unroll
            for (int i = 0; i < 4; i++) {
                int e = tid + i * 256, nn = e >> 4, kk = e & 15;
                pw[i] = (k1 + kk < K && n0 + nn < N) ? W[(size_t)(n0 + nn) * K + k1 + kk] : 0.f;
            }
        }

#pragma unroll
        for (int kk = 0; kk < 16; kk++) {
            float a[8], b[4];
            *reinterpret_cast<float4*>(a)     = *reinterpret_cast<const float4*>(&As[kk][ty * 8]);
            *reinterpret_cast<float4*>(a + 4) = *reinterpret_cast<const float4*>(&As[kk][ty * 8 + 4]);
            *reinterpret_cast<float4*>(b)     = *reinterpret_cast<const float4*>(&Ws[kk][tx * 4]);
#pragma unroll
            for (int i = 0; i < 8; i++)
#pragma unroll
                for (int j = 0; j < 4; j++) acc[i][j] += a[i] * b[j];
        }
        __syncthreads();
    }

#pragma unroll
    for (int i = 0; i < 8; i++) {
        int m = m0 + ty * 8 + i;
#pragma unroll
        for (int j = 0; j < 4; j++) {
            int n = n0 + tx * 4 + j;
            if (n < N) {
                float v = acc[i][j];
                if (bias1) v += bias1[n];
                if (bias2) v += bias2[n];
                if (act == 1) v = fmaxf(v, 0.f) + log1pf(__expf(-fabsf(v)));
                C[(size_t)m * ldc + n] = v;
            }
        }
    }
}

// ------------------------- LSTM dual-batch scan body (one block = dir x batch-pair) ---
// 256 threads; thread = one gate row for TWO batches (b0 = 2*bp, b1 = b0+1).
// Weights w2[32] are SHARED between the two recurrences; two accumulator sets give
// 8 independent FFMA chains that hide each other's latency. One barrier per step.
// lane layout: gate = lane>>3, j = warp*8 + (lane&7) -> shfl gate exchange per batch.
// Sigmoid gates pre-scaled by 0.5: sigmoid(x)=0.5*tanh(x/2)+0.5. tanh direct.
// pre: [NR, 512] (cols dir*256 + gate*64 + j), Whh: [4,2,256,64], out: [NR,128]
__device__ __forceinline__ void lstm_body2(
    int bx, const float* __restrict__ pre, const float* __restrict__ Whh,
    float* __restrict__ out, int layer)
{
    __shared__ __align__(16) float hsh[2][2][64];   // [phase][batch][j]

    const int dir = bx >> 1;
    const int bp  = bx & 1;
    const int tid = threadIdx.x;
    const int w   = tid >> 5;
    const int l   = tid & 31;
    const int gate = l >> 3;
    const int j    = w * 8 + (l & 7);
    const int row  = gate * 64 + j;

    const float scale = (gate == 2) ? 1.f : 0.5f;

    const float* wp = Whh + (size_t)(((layer * 2 + dir) * 256 + row)) * 64;
    unsigned long long w2[32];
#pragma unroll
    for (int k = 0; k < 32; k++) w2[k] = pk2(wp[2 * k] * scale, wp[2 * k + 1] * scale);

    ((float*)hsh)[tid] = 0.f;    // zero all 256 floats
    float c0 = 0.f, c1 = 0.f;
    __syncthreads();

    const int prebase = dir * 256 + row;
    const int tstep   = dir ? -NB : NB;
    int r = (dir ? (SEQ - 1) : 0) * NB + bp * 2;    // batch b0; b1 = r+1
    int p = 0;

    float pv0 = __ldg(pre + (size_t)r * 512 + prebase) * scale;
    float pv1 = __ldg(pre + (size_t)(r + 1) * 512 + prebase) * scale;

    for (int s = 0; s < SEQ; s++) {
        int rn = r + ((s < SEQ - 1) ? tstep : 0);
        float npv0 = __ldg(pre + (size_t)rn * 512 + prebase) * scale;
        float npv1 = __ldg(pre + (size_t)(rn + 1) * 512 + prebase) * scale;

        unsigned long long a0 = pk2(pv0, 0.f), a1 = 0ull, a2 = 0ull, a3 = 0ull;
        unsigned long long d0 = pk2(pv1, 0.f), d1 = 0ull, d2 = 0ull, d3 = 0ull;
        const float* h0 = hsh[p][0];
        const float* h1 = hsh[p][1];
#pragma unroll
        for (int k = 0; k < 8; k++) {
            ulonglong2 x01 = *reinterpret_cast<const ulonglong2*>(h0 + k * 8);
            ulonglong2 x23 = *reinterpret_cast<const ulonglong2*>(h0 + k * 8 + 4);
            ulonglong2 y01 = *reinterpret_cast<const ulonglong2*>(h1 + k * 8);
            ulonglong2 y23 = *reinterpret_cast<const ulonglong2*>(h1 + k * 8 + 4);
            a0 = ffma2(w2[4 * k],     x01.x, a0);
            a1 = ffma2(w2[4 * k + 1], x01.y, a1);
            a2 = ffma2(w2[4 * k + 2], x23.x, a2);
            a3 = ffma2(w2[4 * k + 3], x23.y, a3);
            d0 = ffma2(w2[4 * k],     y01.x, d0);
            d1 = ffma2(w2[4 * k + 1], y01.y, d1);
            d2 = ffma2(w2[4 * k + 2], y23.x, d2);
            d3 = ffma2(w2[4 * k + 3], y23.y, d3);
        }
        float2 gsa = upk2(fadd2(fadd2(a0, a1), fadd2(a2, a3)));
        float2 gsd = upk2(fadd2(fadd2(d0, d1), fadd2(d2, d3)));
        float gv0 = gsa.x + gsa.y;
        float gv1 = gsd.x + gsd.y;

        float v8_0  = __shfl_xor_sync(0xffffffffu, gv0, 8);
        float v8_1  = __shfl_xor_sync(0xffffffffu, gv1, 8);
        float v16_0 = __shfl_xor_sync(0xffffffffu, gv0, 16);
        float v16_1 = __shfl_xor_sync(0xffffffffu, gv1, 16);
        float v24_0 = __shfl_xor_sync(0xffffffffu, gv0, 24);
        float v24_1 = __shfl_xor_sync(0xffffffffu, gv1, 24);

        if (l < 8) {
            // batch 0: gv0 = i/2, v8_0 = f/2, v16_0 = g, v24_0 = o/2
            float iv0 = fmaf(0.5f, tanha(gv0),  0.5f);
            float fv0 = fmaf(0.5f, tanha(v8_0), 0.5f);
            float gg0 = tanha(v16_0);
            float ov0 = fmaf(0.5f, tanha(v24_0), 0.5f);
            float iv1 = fmaf(0.5f, tanha(gv1),  0.5f);
            float fv1 = fmaf(0.5f, tanha(v8_1), 0.5f);
            float gg1 = tanha(v16_1);
            float ov1 = fmaf(0.5f, tanha(v24_1), 0.5f);
            c0 = fmaf(fv0, c0, iv0 * gg0);
            c1 = fmaf(fv1, c1, iv1 * gg1);
            float h_0 = ov0 * tanha(c0);
            float h_1 = ov1 * tanha(c1);
            hsh[p ^ 1][0][j] = h_0;
            hsh[p ^ 1][1][j] = h_1;
            out[(size_t)r * 128 + dir * 64 + j]       = h_0;
            out[(size_t)(r + 1) * 128 + dir * 64 + j] = h_1;
        }
        __syncthreads();

        pv0 = npv0; pv1 = npv1;
        r += tstep;
        p ^= 1;
    }
}

// ------------------------- mamba scan body (one block = (b, d-group of 32)) -----
// dt projection (K=8) + softplus fused inline.
__device__ __forceinline__ void mamba_body(
    int bx,
    const float* __restrict__ dbc,   // [NR,136] : [0:8)=dt_r, [8:72)=B, [72:136)=C
    const float* __restrict__ dtW,   // [256,8]
    const float* __restrict__ dtb,   // [256]
    const float* __restrict__ xcb,   // [NR,256]
    const float* __restrict__ xz,    // [NR,512], z at col 256+
    const float* __restrict__ A_log, // [256,64]
    const float* __restrict__ Dsk,   // [256]
    float* __restrict__ ymid)        // [NR,256]
{
    const int b  = bx >> 3, dg = bx & 7;
    const int tid = threadIdx.x;
    const int dl = tid >> 3, sc = tid & 7;
    const int d  = dg * 32 + dl;
    const int s0 = sc * 8;
    const float L2E = 1.4426950408889634f;

    float a2[8];
#pragma unroll
    for (int i = 0; i < 8; i++)
        a2[i] = -__expf(A_log[(size_t)d * 64 + s0 + i]) * L2E;
    const float dval = Dsk[d];

    float dtw[8];
#pragma unroll
    for (int i = 0; i < 8; i++) dtw[i] = dtW[d * 8 + i];
    const float dtbv = dtb[d];

    float h[8];
#pragma unroll
    for (int i = 0; i < 8; i++) h[i] = 0.f;

    int r = b;
    float4 D0 = *reinterpret_cast<const float4*>(dbc + (size_t)r * 136);
    float4 D1 = *reinterpret_cast<const float4*>(dbc + (size_t)r * 136 + 4);
    float4 B0 = *reinterpret_cast<const float4*>(dbc + (size_t)r * 136 + 8  + s0);
    float4 B1 = *reinterpret_cast<const float4*>(dbc + (size_t)r * 136 + 12 + s0);
    float4 C0 = *reinterpret_cast<const float4*>(dbc + (size_t)r * 136 + 72 + s0);
    float4 C1 = *reinterpret_cast<const float4*>(dbc + (size_t)r * 136 + 76 + s0);
    float xcv = xcb[(size_t)r * 256 + d];
    float zv  = xz [(size_t)r * 512 + 256 + d];

    for (int t = 0; t < SEQ; t++) {
        int rn = r + ((t < SEQ - 1) ? NB : 0);
        float4 nD0 = *reinterpret_cast<const float4*>(dbc + (size_t)rn * 136);
        float4 nD1 = *reinterpret_cast<const float4*>(dbc + (size_t)rn * 136 + 4);
        float4 nB0 = *reinterpret_cast<const float4*>(dbc + (size_t)rn * 136 + 8  + s0);
        float4 nB1 = *reinterpret_cast<const float4*>(dbc + (size_t)rn * 136 + 12 + s0);
        float4 nC0 = *reinterpret_cast<const float4*>(dbc + (size_t)rn * 136 + 72 + s0);
        float4 nC1 = *reinterpret_cast<const float4*>(dbc + (size_t)rn * 136 + 76 + s0);
        float nxc = xcb[(size_t)rn * 256 + d];
        float nz  = xz [(size_t)rn * 512 + 256 + d];

        float xdt = dtbv;
        xdt = fmaf(D0.x, dtw[0], xdt); xdt = fmaf(D0.y, dtw[1], xdt);
        xdt = fmaf(D0.z, dtw[2], xdt); xdt = fmaf(D0.w, dtw[3], xdt);
        xdt = fmaf(D1.x, dtw[4], xdt); xdt = fmaf(D1.y, dtw[5], xdt);
        xdt = fmaf(D1.z, dtw[6], xdt); xdt = fmaf(D1.w, dtw[7], xdt);
        float dtv = fmaxf(xdt, 0.f) + log1pf(__expf(-fabsf(xdt)));

        float Bv[8] = {B0.x, B0.y, B0.z, B0.w, B1.x, B1.y, B1.z, B1.w};
        float Cv[8] = {C0.x, C0.y, C0.z, C0.w, C1.x, C1.y, C1.z, C1.w};
        float dtx = dtv * xcv;
        float part = 0.f;
#pragma unroll
        for (int i = 0; i < 8; i++) {
            float e = ex2f(dtv * a2[i]);
            h[i] = e * h[i] + dtx * Bv[i];
            part += h[i] * Cv[i];
        }
        part += __shfl_xor_sync(0xffffffffu, part, 1);
        part += __shfl_xor_sync(0xffffffffu, part, 2);
        part += __shfl_xor_sync(0xffffffffu, part, 4);
        if (sc == 0) {
            float y = part + xcv * dval;
            y *= zv * sigm(zv);
            ymid[(size_t)r * 256 + d] = y;
        }

        D0 = nD0; D1 = nD1;
        B0 = nB0; B1 = nB1; C0 = nC0; C1 = nC1;
        xcv = nxc; zv = nz;
        r += NB;
    }
}

// ------------------------- combined: LSTM layer 0 (4 dual-batch blocks) + mamba -------
__global__ __launch_bounds__(256, 1) void scan_l0_mamba(
    const float* __restrict__ preL, const float* __restrict__ Whh, float* __restrict__ lstm_out,
    const float* __restrict__ dbc, const float* __restrict__ dtW, const float* __restrict__ dtb,
    const float* __restrict__ xcb, const float* __restrict__ xz,
    const float* __restrict__ A_log, const float* __restrict__ Dsk,
    float* __restrict__ ymid)
{
    if (blockIdx.x < 4) lstm_body2(blockIdx.x, preL, Whh, lstm_out, 0);
    else                mamba_body(blockIdx.x - 4, dbc, dtW, dtb, xcb, xz, A_log, Dsk, ymid);
}

// ------------------------- standalone LSTM layer (4 dual-batch blocks) ----------
__global__ __launch_bounds__(256, 1) void lstm_layer(
    const float* __restrict__ pre, const float* __restrict__ Whh,
    float* __restrict__ out, int layer)
{
    lstm_body2(blockIdx.x, pre, Whh, out, layer);
}

// ------------------------- causal depthwise conv + silu -------------------------
__global__ void conv_silu(const float* __restrict__ xz, const float* __restrict__ cw,
                          const float* __restrict__ cb, float* __restrict__ xc)
{
    int idx = blockIdx.x * 256 + threadIdx.x;       // < NR*256
    int d = idx & 255;
    int r = idx >> 8;
    int t = r >> 2, b = r & 3;
    float acc = cb[d];
#pragma unroll
    for (int k = 0; k < 4; k++) {
        int tt = t - 3 + k;
        if (tt >= 0) acc += xz[(size_t)(tt * NB + b) * 512 + d] * cw[d * 4 + k];
    }
    xc[idx] = acc * sigm(acc);
}

// ------------------------- fusion: LN + gate + mix -------------------------
__global__ __launch_bounds__(256) void fusion(
    const float* __restrict__ lstm, const float* __restrict__ mamba,
    const float* __restrict__ lnw, const float* __restrict__ lnb,
    const float* __restrict__ gW, const float* __restrict__ gb,
    float* __restrict__ out)
{
    int tid  = threadIdx.x;
    int lane = tid & 31;
    int wr   = tid >> 5;
    int r    = blockIdx.x * 8 + wr;

    float4 lv = *reinterpret_cast<const float4*>(lstm  + (size_t)r * 128 + lane * 4);
    float4 mv = *reinterpret_cast<const float4*>(mamba + (size_t)r * 128 + lane * 4);
    float lvv[4] = {lv.x, lv.y, lv.z, lv.w};
    float mvv[4] = {mv.x, mv.y, mv.z, mv.w};

    float s = 0.f, q = 0.f;
#pragma unroll
    for (int i = 0; i < 4; i++) {
        s += lvv[i] + mvv[i];
        q += lvv[i] * lvv[i] + mvv[i] * mvv[i];
    }
#pragma unroll
    for (int o = 16; o; o >>= 1) {
        s += __shfl_xor_sync(0xffffffffu, s, o);
        q += __shfl_xor_sync(0xffffffffu, q, o);
    }
    float mu   = s * (1.f / 256.f);
    float var  = q * (1.f / 256.f) - mu * mu;
    float rstd = rsqrtf(var + 1e-5f);

    float gd = 0.f;
#pragma unroll
    for (int i = 0; i < 4; i++) {
        int cl = lane * 4 + i;
        gd += ((lvv[i] - mu) * rstd * lnw[cl] + lnb[cl]) * gW[cl];
        int cm = 128 + cl;
        gd += ((mvv[i] - mu) * rstd * lnw[cm] + lnb[cm]) * gW[cm];
    }
#pragma unroll
    for (int o = 16; o; o >>= 1) gd += __shfl_xor_sync(0xffffffffu, gd, o);

    float gate = sigm(gd + gb[0]);
    float4 ov;
    ov.x = gate * lvv[0] + (1.f - gate) * mvv[0];
    ov.y = gate * lvv[1] + (1.f - gate) * mvv[1];
    ov.z = gate * lvv[2] + (1.f - gate) * mvv[2];
    ov.w = gate * lvv[3] + (1.f - gate) * mvv[3];
    *reinterpret_cast<float4*>(out + (size_t)r * 128 + lane * 4) = ov;
}

// ------------------------- launch -------------------------
extern "C" void kernel_launch(void* const* d_in, const int* in_sizes, int n_in,
                              void* d_out, int out_size)
{
    const float* x      = (const float*)d_in[0];   // [2048,4,23]
    const float* Wih0   = (const float*)d_in[1];   // [2,256,23]
    const float* WihR   = (const float*)d_in[2];   // [3,2,256,128]
    const float* Whh    = (const float*)d_in[3];   // [4,2,256,64]
    const float* bih    = (const float*)d_in[4];   // [4,2,256]
    const float* bhh    = (const float*)d_in[5];   // [4,2,256]
    const float* mprojW = (const float*)d_in[6];   // [128,23]
    const float* mprojb = (const float*)d_in[7];   // [128]
    const float* inprW  = (const float*)d_in[8];   // [512,128]
    const float* convw  = (const float*)d_in[9];   // [256,1,4]
    const float* convb  = (const float*)d_in[10];  // [256]
    const float* xprW   = (const float*)d_in[11];  // [136,256]
    const float* dtW    = (const float*)d_in[12];  // [256,8]
    const float* dtb    = (const float*)d_in[13];  // [256]
    const float* Alog   = (const float*)d_in[14];  // [256,64]
    const float* Dsk    = (const float*)d_in[15];  // [256]
    const float* outprW = (const float*)d_in[16];  // [128,256]
    const float* lnw    = (const float*)d_in[17];  // [256]
    const float* lnb    = (const float*)d_in[18];  // [256]
    const float* gW     = (const float*)d_in[19];  // [1,256]
    const float* gb     = (const float*)d_in[20];  // [1]
    float* out = (float*)d_out;

    float *preL, *lstmA, *lstmB, *xm, *xz, *xc, *dbc, *ymid, *mamba;
    cudaGetSymbolAddress((void**)&preL,  g_preL);
    cudaGetSymbolAddress((void**)&lstmA, g_lstmA);
    cudaGetSymbolAddress((void**)&lstmB, g_lstmB);
    cudaGetSymbolAddress((void**)&xm,    g_xm);
    cudaGetSymbolAddress((void**)&xz,    g_xz);
    cudaGetSymbolAddress((void**)&xc,    g_xc);
    cudaGetSymbolAddress((void**)&dbc,   g_dbc);
    cudaGetSymbolAddress((void**)&ymid,  g_ymid);
    cudaGetSymbolAddress((void**)&mamba, g_mamba);

    const int M = NR;

    // 1: LSTM layer-0 preactivations (bias = bih[0]+bhh[0] fused in epilogue)
    gemm_tn<<<dim3(M/128, 8), 256>>>(x, 23, Wih0, bih, bhh, preL, 512, M, 512, 23, 0);
    // 2: mamba input projection
    gemm_tn<<<dim3(M/128, 2), 256>>>(x, 23, mprojW, mprojb, nullptr, xm, 128, M, 128, 23, 0);
    // 3: mamba in_proj
    gemm_tn<<<dim3(M/128, 8), 256>>>(xm, 128, inprW, nullptr, nullptr, xz, 512, M, 512, 128, 0);
    // 4: causal conv + silu
    conv_silu<<<(M*256)/256, 256>>>(xz, convw, convb, xc);
    // 5: x_proj
    gemm_tn<<<dim3(M/128, 3), 256>>>(xc, 256, xprW, nullptr, nullptr, dbc, 136, M, 136, 256, 0);
    // 6: LSTM layer 0 scan (4 dual-batch blocks) + mamba selective scan (32 blocks)
    scan_l0_mamba<<<36, 256>>>(preL, Whh, lstmA, dbc, dtW, dtb, xc, xz, Alog, Dsk, ymid);
    // 7: mamba out_proj
    gemm_tn<<<dim3(M/128, 2), 256>>>(ymid, 256, outprW, nullptr, nullptr, mamba, 128, M, 128, 256, 0);

    // LSTM layers 1..3
    gemm_tn<<<dim3(M/128, 8), 256>>>(lstmA, 128, WihR + 0*65536, bih + 512,  bhh + 512,  preL, 512, M, 512, 128, 0);
    lstm_layer<<<4, 256>>>(preL, Whh, lstmB, 1);
    gemm_tn<<<dim3(M/128, 8), 256>>>(lstmB, 128, WihR + 1*65536, bih + 1024, bhh + 1024, preL, 512, M, 512, 128, 0);
    lstm_layer<<<4, 256>>>(preL, Whh, lstmA, 2);
    gemm_tn<<<dim3(M/128, 8), 256>>>(lstmA, 128, WihR + 2*65536, bih + 1536, bhh + 1536, preL, 512, M, 512, 128, 0);
    lstm_layer<<<4, 256>>>(preL, Whh, lstmB, 3);

    // fusion
    fusion<<<M/8, 256>>>(lstmB, mamba, lnw, lnb, gW, gb, out);
}

// round 14
// speedup vs baseline: 1.5171x; 1.5171x over previous
#include <cuda_runtime.h>
#include <cuda_bf16.h>

#define SEQ 2048
#define NB  4
#define NR  (SEQ*NB)   // 8192 rows, r = t*NB + b

// ------------------------- scratch (device globals) -------------------------
__device__ float g_preL [NR*512];
__device__ float g_lstmA[NR*128];
__device__ float g_lstmB[NR*128];
__device__ float g_w2   [512*23 + 512];   // fused in_proj weights + bias
__device__ float g_xz   [NR*512];
__device__ float g_xc   [NR*256];
__device__ float g_dbc  [NR*136];
__device__ float g_ymid [NR*256];
__device__ float g_mamba[NR*128];

// ------------------------- helpers -------------------------
__device__ __forceinline__ unsigned long long ffma2(unsigned long long a, unsigned long long b, unsigned long long c){
    unsigned long long d; asm("fma.rn.f32x2 %0, %1, %2, %3;" : "=l"(d) : "l"(a), "l"(b), "l"(c)); return d;
}
__device__ __forceinline__ unsigned long long fadd2(unsigned long long a, unsigned long long b){
    unsigned long long d; asm("add.rn.f32x2 %0, %1, %2;" : "=l"(d) : "l"(a), "l"(b)); return d;
}
__device__ __forceinline__ unsigned long long pk2(float lo, float hi){
    unsigned long long d; asm("mov.b64 %0, {%1, %2};" : "=l"(d) : "f"(lo), "f"(hi)); return d;
}
__device__ __forceinline__ float2 upk2(unsigned long long v){
    float2 r; asm("mov.b64 {%0, %1}, %2;" : "=f"(r.x), "=f"(r.y) : "l"(v)); return r;
}
__device__ __forceinline__ float ex2f(float x){
    float y; asm("ex2.approx.f32 %0, %1;" : "=f"(y) : "f"(x)); return y;
}
__device__ __forceinline__ float rcpf(float x){
    float y; asm("rcp.approx.f32 %0, %1;" : "=f"(y) : "f"(x)); return y;
}
__device__ __forceinline__ float tanha(float x){
    float y; asm("tanh.approx.f32 %0, %1;" : "=f"(y) : "f"(x)); return y;
}
__device__ __forceinline__ float sigm(float x){
    return rcpf(1.f + ex2f(-1.4426950408889634f * x));
}

// ------------------------- weight prep: W2 = inprW @ mprojW, c2 = inprW @ mprojb ----
// W2: [512,23], c2: [512]. 512*24 threads, 128-MAC dot each.
__global__ void prep_w2(const float* __restrict__ inprW, const float* __restrict__ mprojW,
                        const float* __restrict__ mprojb, float* __restrict__ W2c)
{
    int idx = blockIdx.x * 256 + threadIdx.x;     // < 512*24
    int n = idx / 24, k = idx % 24;
    if (n >= 512) return;
    const float* wr = inprW + n * 128;
    float s = 0.f;
    if (k < 23) {
        for (int m = 0; m < 128; m++) s = fmaf(wr[m], mprojW[m * 23 + k], s);
        W2c[n * 23 + k] = s;
    } else {
        for (int m = 0; m < 128; m++) s = fmaf(wr[m], mprojb[m], s);
        W2c[512 * 23 + n] = s;
    }
}

// ------------------------- GEMM: C = A @ W^T (+bias1+bias2)(+act) ------------------
// tile 128(M) x 64(N), 256 threads, microtile 8x4, double-buffered k-tiles.
// A: [M, lda] row-major (first K cols), W: [N, K], C: [M, ldc]. M % 128 == 0.
// act: 0 = none, 1 = softplus
__global__ __launch_bounds__(256, 3) void gemm_tn(
    const float* __restrict__ A, int lda,
    const float* __restrict__ W,
    const float* __restrict__ bias1,
    const float* __restrict__ bias2,
    float* __restrict__ C, int ldc,
    int M, int N, int K, int act)
{
    __shared__ float As[16][136];
    __shared__ float Ws[16][72];
    const int tid = threadIdx.x;
    const int tx = tid & 15, ty = tid >> 4;
    const int m0 = blockIdx.x * 128, n0 = blockIdx.y * 64;

    float acc[8][4];
#pragma unroll
    for (int i = 0; i < 8; i++)
#pragma unroll
        for (int j = 0; j < 4; j++) acc[i][j] = 0.f;

    float pa[8], pw[4];
#pragma unroll
    for (int i = 0; i < 8; i++) {
        int e = tid + i * 256, mm = e >> 4, kk = e & 15;
        pa[i] = (kk < K) ? A[(size_t)(m0 + mm) * lda + kk] : 0.f;
    }
#pragma unroll
    for (int i = 0; i < 4; i++) {
        int e = tid + i * 256, nn = e >> 4, kk = e & 15;
        pw[i] = (kk < K && n0 + nn < N) ? W[(size_t)(n0 + nn) * K + kk] : 0.f;
    }

    for (int k0 = 0; k0 < K; k0 += 16) {
#pragma unroll
        for (int i = 0; i < 8; i++) {
            int e = tid + i * 256;
            As[e & 15][e >> 4] = pa[i];
        }
#pragma unroll
        for (int i = 0; i < 4; i++) {
            int e = tid + i * 256;
            Ws[e & 15][e >> 4] = pw[i];
        }
        __syncthreads();

        int k1 = k0 + 16;
        if (k1 < K) {
#pragma unroll
            for (int i = 0; i < 8; i++) {
                int e = tid + i * 256, mm = e >> 4, kk = e & 15;
                pa[i] = (k1 + kk < K) ? A[(size_t)(m0 + mm) * lda + k1 + kk] : 0.f;
            }
#pragma unroll
            for (int i = 0; i < 4; i++) {
                int e = tid + i * 256, nn = e >> 4, kk = e & 15;
                pw[i] = (k1 + kk < K && n0 + nn < N) ? W[(size_t)(n0 + nn) * K + k1 + kk] : 0.f;
            }
        }

#pragma unroll
        for (int kk = 0; kk < 16; kk++) {
            float a[8], b[4];
            *reinterpret_cast<float4*>(a)     = *reinterpret_cast<const float4*>(&As[kk][ty * 8]);
            *reinterpret_cast<float4*>(a + 4) = *reinterpret_cast<const float4*>(&As[kk][ty * 8 + 4]);
            *reinterpret_cast<float4*>(b)     = *reinterpret_cast<const float4*>(&Ws[kk][tx * 4]);
#pragma unroll
            for (int i = 0; i < 8; i++)
#pragma unroll
                for (int j = 0; j < 4; j++) acc[i][j] += a[i] * b[j];
        }
        __syncthreads();
    }

#pragma unroll
    for (int i = 0; i < 8; i++) {
        int m = m0 + ty * 8 + i;
#pragma unroll
        for (int j = 0; j < 4; j++) {
            int n = n0 + tx * 4 + j;
            if (n < N) {
                float v = acc[i][j];
                if (bias1) v += bias1[n];
                if (bias2) v += bias2[n];
                if (act == 1) v = fmaxf(v, 0.f) + log1pf(__expf(-fabsf(v)));
                C[(size_t)m * ldc + n] = v;
            }
        }
    }
}

// ------------------------- LSTM scan body (one block = dir x batch) ---------
// 256 threads; thread = one gate row. lane layout: gate = lane>>3, j = warp*8 + (lane&7)
// so all 4 gates of j live in one warp -> shfl exchange of raw preacts.
// Sigmoid gates (i,f,o) have weights/preacts PRE-SCALED by 0.5:
// sigmoid(x) = 0.5*tanh(x/2)+0.5 (1 MUFU). tanh gate + tanh(c): tanh.approx direct.
// pre: [NR, 512] (cols dir*256 + gate*64 + j), Whh: [4,2,256,64], out: [NR,128]
__device__ __forceinline__ void lstm_body(
    int bx, const float* __restrict__ pre, const float* __restrict__ Whh,
    float* __restrict__ out, int layer)
{
    __shared__ __align__(16) float hsh[2][64];

    const int dir = bx >> 2;
    const int b   = bx & 3;
    const int tid = threadIdx.x;
    const int w   = tid >> 5;
    const int l   = tid & 31;
    const int gate = l >> 3;
    const int j    = w * 8 + (l & 7);
    const int row  = gate * 64 + j;

    const float scale = (gate == 2) ? 1.f : 0.5f;   // tanh gate full, sigmoid gates halved

    const float* wp = Whh + (size_t)(((layer * 2 + dir) * 256 + row)) * 64;
    unsigned long long w2[32];
#pragma unroll
    for (int k = 0; k < 32; k++) w2[k] = pk2(wp[2 * k] * scale, wp[2 * k + 1] * scale);

    if (tid < 64) { hsh[0][tid] = 0.f; hsh[1][tid] = 0.f; }
    float c = 0.f;
    __syncthreads();

    const int prebase = dir * 256 + row;
    const int tstep   = dir ? -NB : NB;
    int r = (dir ? (SEQ - 1) : 0) * NB + b;
    int p = 0;

    float pv = __ldg(pre + (size_t)r * 512 + prebase) * scale;

    for (int s = 0; s < SEQ; s++) {
        int rn = r + ((s < SEQ - 1) ? tstep : 0);
        float npv = __ldg(pre + (size_t)rn * 512 + prebase) * scale;

        unsigned long long a0 = pk2(pv, 0.f);
        unsigned long long a1 = 0ull, a2 = 0ull, a3 = 0ull;
        const float* hrow = hsh[p];
#pragma unroll
        for (int k = 0; k < 8; k++) {
            ulonglong2 h01 = *reinterpret_cast<const ulonglong2*>(hrow + k * 8);
            ulonglong2 h23 = *reinterpret_cast<const ulonglong2*>(hrow + k * 8 + 4);
            a0 = ffma2(w2[4 * k],     h01.x, a0);
            a1 = ffma2(w2[4 * k + 1], h01.y, a1);
            a2 = ffma2(w2[4 * k + 2], h23.x, a2);
            a3 = ffma2(w2[4 * k + 3], h23.y, a3);
        }
        float2 gs = upk2(fadd2(fadd2(a0, a1), fadd2(a2, a3)));
        float gv = gs.x + gs.y;     // scaled preactivation for this gate row

        float v8  = __shfl_xor_sync(0xffffffffu, gv, 8);
        float v16 = __shfl_xor_sync(0xffffffffu, gv, 16);
        float v24 = __shfl_xor_sync(0xffffffffu, gv, 24);

        if (l < 8) {
            // lanes 0-7: gv = i/2, v8 = f/2, v16 = g, v24 = o/2 (pre-scaled)
            float iv = fmaf(0.5f, tanha(gv),  0.5f);
            float fv = fmaf(0.5f, tanha(v8),  0.5f);
            float gg = tanha(v16);
            float ov = fmaf(0.5f, tanha(v24), 0.5f);
            c = fmaf(fv, c, iv * gg);
            float h = ov * tanha(c);
            hsh[p ^ 1][j] = h;
            out[(size_t)r * 128 + dir * 64 + j] = h;
        }
        __syncthreads();

        pv = npv;
        r += tstep;
        p ^= 1;
    }
}

// ------------------------- mamba scan body (one block = (b, d-group of 32)) -----
// dt projection (K=8) + softplus fused inline.
__device__ __forceinline__ void mamba_body(
    int bx,
    const float* __restrict__ dbc,   // [NR,136] : [0:8)=dt_r, [8:72)=B, [72:136)=C
    const float* __restrict__ dtW,   // [256,8]
    const float* __restrict__ dtb,   // [256]
    const float* __restrict__ xcb,   // [NR,256]
    const float* __restrict__ xz,    // [NR,512], z at col 256+
    const float* __restrict__ A_log, // [256,64]
    const float* __restrict__ Dsk,   // [256]
    float* __restrict__ ymid)        // [NR,256]
{
    const int b  = bx >> 3, dg = bx & 7;
    const int tid = threadIdx.x;
    const int dl = tid >> 3, sc = tid & 7;
    const int d  = dg * 32 + dl;
    const int s0 = sc * 8;
    const float L2E = 1.4426950408889634f;

    float a2[8];
#pragma unroll
    for (int i = 0; i < 8; i++)
        a2[i] = -__expf(A_log[(size_t)d * 64 + s0 + i]) * L2E;
    const float dval = Dsk[d];

    float dtw[8];
#pragma unroll
    for (int i = 0; i < 8; i++) dtw[i] = dtW[d * 8 + i];
    const float dtbv = dtb[d];

    float h[8];
#pragma unroll
    for (int i = 0; i < 8; i++) h[i] = 0.f;

    int r = b;
    float4 D0 = *reinterpret_cast<const float4*>(dbc + (size_t)r * 136);
    float4 D1 = *reinterpret_cast<const float4*>(dbc + (size_t)r * 136 + 4);
    float4 B0 = *reinterpret_cast<const float4*>(dbc + (size_t)r * 136 + 8  + s0);
    float4 B1 = *reinterpret_cast<const float4*>(dbc + (size_t)r * 136 + 12 + s0);
    float4 C0 = *reinterpret_cast<const float4*>(dbc + (size_t)r * 136 + 72 + s0);
    float4 C1 = *reinterpret_cast<const float4*>(dbc + (size_t)r * 136 + 76 + s0);
    float xcv = xcb[(size_t)r * 256 + d];
    float zv  = xz [(size_t)r * 512 + 256 + d];

    for (int t = 0; t < SEQ; t++) {
        int rn = r + ((t < SEQ - 1) ? NB : 0);
        float4 nD0 = *reinterpret_cast<const float4*>(dbc + (size_t)rn * 136);
        float4 nD1 = *reinterpret_cast<const float4*>(dbc + (size_t)rn * 136 + 4);
        float4 nB0 = *reinterpret_cast<const float4*>(dbc + (size_t)rn * 136 + 8  + s0);
        float4 nB1 = *reinterpret_cast<const float4*>(dbc + (size_t)rn * 136 + 12 + s0);
        float4 nC0 = *reinterpret_cast<const float4*>(dbc + (size_t)rn * 136 + 72 + s0);
        float4 nC1 = *reinterpret_cast<const float4*>(dbc + (size_t)rn * 136 + 76 + s0);
        float nxc = xcb[(size_t)rn * 256 + d];
        float nz  = xz [(size_t)rn * 512 + 256 + d];

        float xdt = dtbv;
        xdt = fmaf(D0.x, dtw[0], xdt); xdt = fmaf(D0.y, dtw[1], xdt);
        xdt = fmaf(D0.z, dtw[2], xdt); xdt = fmaf(D0.w, dtw[3], xdt);
        xdt = fmaf(D1.x, dtw[4], xdt); xdt = fmaf(D1.y, dtw[5], xdt);
        xdt = fmaf(D1.z, dtw[6], xdt); xdt = fmaf(D1.w, dtw[7], xdt);
        float dtv = fmaxf(xdt, 0.f) + log1pf(__expf(-fabsf(xdt)));

        float Bv[8] = {B0.x, B0.y, B0.z, B0.w, B1.x, B1.y, B1.z, B1.w};
        float Cv[8] = {C0.x, C0.y, C0.z, C0.w, C1.x, C1.y, C1.z, C1.w};
        float dtx = dtv * xcv;
        float part = 0.f;
#pragma unroll
        for (int i = 0; i < 8; i++) {
            float e = ex2f(dtv * a2[i]);
            h[i] = e * h[i] + dtx * Bv[i];
            part += h[i] * Cv[i];
        }
        part += __shfl_xor_sync(0xffffffffu, part, 1);
        part += __shfl_xor_sync(0xffffffffu, part, 2);
        part += __shfl_xor_sync(0xffffffffu, part, 4);
        if (sc == 0) {
            float y = part + xcv * dval;
            y *= zv * sigm(zv);
            ymid[(size_t)r * 256 + d] = y;
        }

        D0 = nD0; D1 = nD1;
        B0 = nB0; B1 = nB1; C0 = nC0; C1 = nC1;
        xcv = nxc; zv = nz;
        r += NB;
    }
}

// ------------------------- combined: LSTM layer 0 + mamba scan -------------------------
__global__ __launch_bounds__(256, 1) void scan_l0_mamba(
    const float* __restrict__ preL, const float* __restrict__ Whh, float* __restrict__ lstm_out,
    const float* __restrict__ dbc, const float* __restrict__ dtW, const float* __restrict__ dtb,
    const float* __restrict__ xcb, const float* __restrict__ xz,
    const float* __restrict__ A_log, const float* __restrict__ Dsk,
    float* __restrict__ ymid)
{
    if (blockIdx.x < 8) lstm_body(blockIdx.x, preL, Whh, lstm_out, 0);
    else                mamba_body(blockIdx.x - 8, dbc, dtW, dtb, xcb, xz, A_log, Dsk, ymid);
}

// ------------------------- standalone LSTM layer -------------------------
__global__ __launch_bounds__(256, 1) void lstm_layer(
    const float* __restrict__ pre, const float* __restrict__ Whh,
    float* __restrict__ out, int layer)
{
    lstm_body(blockIdx.x, pre, Whh, out, layer);
}

// ------------------------- causal depthwise conv + silu -------------------------
__global__ void conv_silu(const float* __restrict__ xz, const float* __restrict__ cw,
                          const float* __restrict__ cb, float* __restrict__ xc)
{
    int idx = blockIdx.x * 256 + threadIdx.x;       // < NR*256
    int d = idx & 255;
    int r = idx >> 8;
    int t = r >> 2, b = r & 3;
    float acc = cb[d];
#pragma unroll
    for (int k = 0; k < 4; k++) {
        int tt = t - 3 + k;
        if (tt >= 0) acc += xz[(size_t)(tt * NB + b) * 512 + d] * cw[d * 4 + k];
    }
    xc[idx] = acc * sigm(acc);
}

// ------------------------- fusion: LN + gate + mix -------------------------
__global__ __launch_bounds__(256) void fusion(
    const float* __restrict__ lstm, const float* __restrict__ mamba,
    const float* __restrict__ lnw, const float* __restrict__ lnb,
    const float* __restrict__ gW, const float* __restrict__ gb,
    float* __restrict__ out)
{
    int tid  = threadIdx.x;
    int lane = tid & 31;
    int wr   = tid >> 5;
    int r    = blockIdx.x * 8 + wr;

    float4 lv = *reinterpret_cast<const float4*>(lstm  + (size_t)r * 128 + lane * 4);
    float4 mv = *reinterpret_cast<const float4*>(mamba + (size_t)r * 128 + lane * 4);
    float lvv[4] = {lv.x, lv.y, lv.z, lv.w};
    float mvv[4] = {mv.x, mv.y, mv.z, mv.w};

    float s = 0.f, q = 0.f;
#pragma unroll
    for (int i = 0; i < 4; i++) {
        s += lvv[i] + mvv[i];
        q += lvv[i] * lvv[i] + mvv[i] * mvv[i];
    }
#pragma unroll
    for (int o = 16; o; o >>= 1) {
        s += __shfl_xor_sync(0xffffffffu, s, o);
        q += __shfl_xor_sync(0xffffffffu, q, o);
    }
    float mu   = s * (1.f / 256.f);
    float var  = q * (1.f / 256.f) - mu * mu;
    float rstd = rsqrtf(var + 1e-5f);

    float gd = 0.f;
#pragma unroll
    for (int i = 0; i < 4; i++) {
        int cl = lane * 4 + i;
        gd += ((lvv[i] - mu) * rstd * lnw[cl] + lnb[cl]) * gW[cl];
        int cm = 128 + cl;
        gd += ((mvv[i] - mu) * rstd * lnw[cm] + lnb[cm]) * gW[cm];
    }
#pragma unroll
    for (int o = 16; o; o >>= 1) gd += __shfl_xor_sync(0xffffffffu, gd, o);

    float gate = sigm(gd + gb[0]);
    float4 ov;
    ov.x = gate * lvv[0] + (1.f - gate) * mvv[0];
    ov.y = gate * lvv[1] + (1.f - gate) * mvv[1];
    ov.z = gate * lvv[2] + (1.f - gate) * mvv[2];
    ov.w = gate * lvv[3] + (1.f - gate) * mvv[3];
    *reinterpret_cast<float4*>(out + (size_t)r * 128 + lane * 4) = ov;
}

// ------------------------- launch -------------------------
extern "C" void kernel_launch(void* const* d_in, const int* in_sizes, int n_in,
                              void* d_out, int out_size)
{
    const float* x      = (const float*)d_in[0];   // [2048,4,23]
    const float* Wih0   = (const float*)d_in[1];   // [2,256,23]
    const float* WihR   = (const float*)d_in[2];   // [3,2,256,128]
    const float* Whh    = (const float*)d_in[3];   // [4,2,256,64]
    const float* bih    = (const float*)d_in[4];   // [4,2,256]
    const float* bhh    = (const float*)d_in[5];   // [4,2,256]
    const float* mprojW = (const float*)d_in[6];   // [128,23]
    const float* mprojb = (const float*)d_in[7];   // [128]
    const float* inprW  = (const float*)d_in[8];   // [512,128]
    const float* convw  = (const float*)d_in[9];   // [256,1,4]
    const float* convb  = (const float*)d_in[10];  // [256]
    const float* xprW   = (const float*)d_in[11];  // [136,256]
    const float* dtW    = (const float*)d_in[12];  // [256,8]
    const float* dtb    = (const float*)d_in[13];  // [256]
    const float* Alog   = (const float*)d_in[14];  // [256,64]
    const float* Dsk    = (const float*)d_in[15];  // [256]
    const float* outprW = (const float*)d_in[16];  // [128,256]
    const float* lnw    = (const float*)d_in[17];  // [256]
    const float* lnb    = (const float*)d_in[18];  // [256]
    const float* gW     = (const float*)d_in[19];  // [1,256]
    const float* gb     = (const float*)d_in[20];  // [1]
    float* out = (float*)d_out;

    float *preL, *lstmA, *lstmB, *w2c, *xz, *xc, *dbc, *ymid, *mamba;
    cudaGetSymbolAddress((void**)&preL,  g_preL);
    cudaGetSymbolAddress((void**)&lstmA, g_lstmA);
    cudaGetSymbolAddress((void**)&lstmB, g_lstmB);
    cudaGetSymbolAddress((void**)&w2c,   g_w2);
    cudaGetSymbolAddress((void**)&xz,    g_xz);
    cudaGetSymbolAddress((void**)&xc,    g_xc);
    cudaGetSymbolAddress((void**)&dbc,   g_dbc);
    cudaGetSymbolAddress((void**)&ymid,  g_ymid);
    cudaGetSymbolAddress((void**)&mamba, g_mamba);

    const int M = NR;

    // 0: fuse mproj into in_proj: W2 = inprW @ mprojW [512,23], c2 = inprW @ mprojb [512]
    prep_w2<<<48, 256>>>(inprW, mprojW, mprojb, w2c);
    // 1: LSTM layer-0 preactivations (bias = bih[0]+bhh[0] fused in epilogue)
    gemm_tn<<<dim3(M/128, 8), 256>>>(x, 23, Wih0, bih, bhh, preL, 512, M, 512, 23, 0);
    // 2: combined mamba input+in_proj: xz = x @ W2^T + c2
    gemm_tn<<<dim3(M/128, 8), 256>>>(x, 23, w2c, w2c + 512*23, nullptr, xz, 512, M, 512, 23, 0);
    // 3: causal conv + silu
    conv_silu<<<(M*256)/256, 256>>>(xz, convw, convb, xc);
    // 4: x_proj
    gemm_tn<<<dim3(M/128, 3), 256>>>(xc, 256, xprW, nullptr, nullptr, dbc, 136, M, 136, 256, 0);
    // 5: LSTM layer 0 scan + mamba selective scan (dt proj fused inline)
    scan_l0_mamba<<<40, 256>>>(preL, Whh, lstmA, dbc, dtW, dtb, xc, xz, Alog, Dsk, ymid);
    // 6: mamba out_proj
    gemm_tn<<<dim3(M/128, 2), 256>>>(ymid, 256, outprW, nullptr, nullptr, mamba, 128, M, 128, 256, 0);

    // LSTM layers 1..3
    gemm_tn<<<dim3(M/128, 8), 256>>>(lstmA, 128, WihR + 0*65536, bih + 512,  bhh + 512,  preL, 512, M, 512, 128, 0);
    lstm_layer<<<8, 256>>>(preL, Whh, lstmB, 1);
    gemm_tn<<<dim3(M/128, 8), 256>>>(lstmB, 128, WihR + 1*65536, bih + 1024, bhh + 1024, preL, 512, M, 512, 128, 0);
    lstm_layer<<<8, 256>>>(preL, Whh, lstmA, 2);
    gemm_tn<<<dim3(M/128, 8), 256>>>(lstmA, 128, WihR + 2*65536, bih + 1536, bhh + 1536, preL, 512, M, 512, 128, 0);
    lstm_layer<<<8, 256>>>(preL, Whh, lstmB, 3);

    // fusion
    fusion<<<M/8, 256>>>(lstmB, mamba, lnw, lnb, gW, gb, out);
}